// round 5
// baseline (speedup 1.0000x reference)
#include <cuda_runtime.h>
#include <cstdint>

// Problem constants
#define B_DIM   16
#define L_DIM   160000
#define N_WT    10
#define WT_LEN  512
#define FIR_TAPS 31
#define WT_TOT  (N_WT * WT_LEN)

// Blocked-scan parameters (XLA ReduceWindowRewriter, base_length = 16)
#define NS1 10000
#define NS2 625
#define NS3 40
#define NS4 3

#define TPB 640            // k_main threads per block (160000 / 640 = 250)

// k_main dynamic smem layout
#define SP_BYTES   (WT_TOT * 8)            // 40960  float2 pair table
#define SATT_BYTES (TPB * 11 * 4)          // 28160  padded attention tile
#define SINC_BYTES (TPB * 4)               // 2560   staged increments
#define SO1_BYTES  (40 * 4)                // 160    O1 predecessors
#define SMEM_BYTES (SP_BYTES + SATT_BYTES + SINC_BYTES + SO1_BYTES)  // 71840

__device__ __forceinline__ float KF() { return (float)(512.0 / 16000.0); }

// Scratch
__device__ float g_S1[B_DIM][NS1];   // 16-block sums of increments
__device__ float g_S2[B_DIM][NS2];   // 16-block sums of S1
__device__ float g_O2[B_DIM][NS2];   // composed inclusive scan at level 2
__device__ float g_wt[WT_TOT];       // FIR-filtered wavetables

// ---------------------------------------------------------------------------
// k_s1: blocks x<40 compute S1 (strict sequential 16-sums of rn(k*pitch))
//       and S2 (strict sequential 16-sums of S1, via block smem).
//       block x==40, y==0 does the FIR instead (circular pad, strict rn).
// ---------------------------------------------------------------------------
__global__ void k_s1(const float* __restrict__ pitch,
                     const float* __restrict__ wtab,
                     const float* __restrict__ firh)
{
    __shared__ float s1s[256];
    __shared__ float sh[FIR_TAPS];

    if (blockIdx.x == 40) {                 // FIR block
        if (blockIdx.y != 0) return;
        if (threadIdx.x < FIR_TAPS) sh[threadIdx.x] = firh[threadIdx.x];
        __syncthreads();
        for (int idx = threadIdx.x; idx < WT_TOT; idx += blockDim.x) {
            int w = idx >> 9;
            int i = idx & 511;
            const float* row = wtab + w * WT_LEN;
            float s = 0.0f;
            #pragma unroll
            for (int k = 0; k < FIR_TAPS; k++) {
                int j = (i + k - 15 + WT_LEN) & 511;
                s = __fadd_rn(s, __fmul_rn(row[j], sh[k]));
            }
            g_wt[idx] = s;
        }
        return;
    }

    const int j = blockIdx.x * 256 + threadIdx.x;
    const int b = blockIdx.y;
    const float k = KF();
    float acc = 0.0f;
    if (j < NS1) {
        const float* P = pitch + b * L_DIM + (j << 4);
        #pragma unroll
        for (int e = 0; e < 16; e++)
            acc = __fadd_rn(acc, __fmul_rn(k, P[e]));
        g_S1[b][j] = acc;
    }
    s1s[threadIdx.x] = acc;
    __syncthreads();

    if (threadIdx.x < 16) {
        int j2 = blockIdx.x * 16 + threadIdx.x;
        if (j2 < NS2) {
            float a2 = 0.0f;
            #pragma unroll
            for (int e = 0; e < 16; e++)
                a2 = __fadd_rn(a2, s1s[(threadIdx.x << 4) + e]);
            g_S2[b][j2] = a2;
        }
    }
}

// ---------------------------------------------------------------------------
// k_scan: per-row (16 blocks) top levels: S2 -> S3 -> S4 -> O4 -> O3 -> O2.
// ---------------------------------------------------------------------------
__global__ void k_scan()
{
    __shared__ float sS2[NS2];
    __shared__ float sS3[NS3];
    __shared__ float sS4[NS4];
    __shared__ float sO4[NS4];
    __shared__ float sO3[NS3];

    const int b   = blockIdx.x;
    const int tid = threadIdx.x;

    if (tid < NS2) sS2[tid] = g_S2[b][tid];
    __syncthreads();

    if (tid < NS3) {                         // S3 (625 padded to 640)
        float acc = 0.0f;
        for (int e = 0; e < 16; e++) {
            int idx = (tid << 4) + e;
            if (idx < NS2) acc = __fadd_rn(acc, sS2[idx]);
        }
        sS3[tid] = acc;
    }
    __syncthreads();

    if (tid < NS4) {                         // S4 (40 padded to 48)
        float acc = 0.0f;
        for (int e = 0; e < 16; e++) {
            int idx = (tid << 4) + e;
            if (idx < NS3) acc = __fadd_rn(acc, sS3[idx]);
        }
        sS4[tid] = acc;
    }
    __syncthreads();

    if (tid == 0) {                          // O4 sequential
        float acc = 0.0f;
        for (int m = 0; m < NS4; m++) {
            acc = __fadd_rn(acc, sS4[m]);
            sO4[m] = acc;
        }
    }
    __syncthreads();

    if (tid < NS3) {                         // O3
        int blk = tid >> 4;
        float acc = 0.0f;
        for (int m = (blk << 4); m <= tid; m++)
            acc = __fadd_rn(acc, sS3[m]);
        sO3[tid] = blk ? __fadd_rn(acc, sO4[blk - 1]) : acc;
    }
    __syncthreads();

    if (tid < NS2) {                         // O2 -> global
        int blk = tid >> 4;
        float acc = 0.0f;
        for (int m = (blk << 4); m <= tid; m++)
            acc = __fadd_rn(acc, sS2[m]);
        g_O2[b][tid] = blk ? __fadd_rn(acc, sO3[blk - 1]) : acc;
    }
}

// ---------------------------------------------------------------------------
// k_main: per block — pair wavetable, padded attention tile (coalesced
// float4 staging), staged increments, O1 predecessors rebuilt on the fly.
// Arithmetic chains bitwise-identical to the verified R3/R4 kernels.
// ---------------------------------------------------------------------------
__global__ void __launch_bounds__(TPB, 3) k_main(
        const float* __restrict__ pitch,
        const float* __restrict__ env,
        const float* __restrict__ att,
        float* __restrict__ out)
{
    extern __shared__ char smem_raw[];
    float2* sp   = (float2*)smem_raw;
    float*  satt = (float*)(smem_raw + SP_BYTES);
    float*  sinc = (float*)(smem_raw + SP_BYTES + SATT_BYTES);
    float*  sO1p = (float*)(smem_raw + SP_BYTES + SATT_BYTES + SINC_BYTES);

    const int tid = threadIdx.x;
    const int b   = blockIdx.y;
    const int t   = blockIdx.x * TPB + tid;   // 250 * 640 == 160000
    const float k = KF();

    // (value, next) pair table
    for (int i = tid; i < WT_TOT; i += TPB) {
        int base_w = i & ~511;
        int j = i & 511;
        sp[i] = make_float2(g_wt[i], g_wt[base_w | ((j + 1) & 511)]);
    }

    // attention tile: coalesced float4 loads, scatter to stride-11 layout
    {
        const float4* ag = (const float4*)(att +
            (size_t)(b * (size_t)L_DIM + (size_t)blockIdx.x * TPB) * N_WT);
        #pragma unroll
        for (int it = 0; it < 3; it++) {
            int i = tid + it * TPB;
            if (i < (TPB * N_WT) / 4) {
                float4 v = ag[i];
                int e = i << 2;
                int q0 = (e    ) / 10; satt[q0*11 + (e     - q0*10)] = v.x;
                int q1 = (e + 1) / 10; satt[q1*11 + (e + 1 - q1*10)] = v.y;
                int q2 = (e + 2) / 10; satt[q2*11 + (e + 2 - q2*10)] = v.z;
                int q3 = (e + 3) / 10; satt[q3*11 + (e + 3 - q3*10)] = v.w;
            }
        }
    }

    // staged increments (16-blocks never straddle tiles: 640 % 16 == 0)
    sinc[tid] = __fmul_rn(k, pitch[b * L_DIM + t]);

    // O1 predecessors for this tile's 40 16-blocks
    if (tid < 40) {
        int m = blockIdx.x * 40 + tid - 1;
        float val = 0.0f;
        if (m >= 0) {
            int blk = m >> 4;
            const float* S1r = g_S1[b];
            float acc = 0.0f;
            for (int q = (blk << 4); q <= m; q++)
                acc = __fadd_rn(acc, S1r[q]);
            val = blk ? __fadd_rn(acc, g_O2[b][blk - 1]) : acc;
        }
        sO1p[tid] = val;
    }
    __syncthreads();

    // strict sequential prefix within the 16-block
    const int r0 = tid & 15;
    const int lb = tid & ~15;
    float acc = 0.0f;
    for (int e = 0; e <= r0; e++)
        acc = __fadd_rn(acc, sinc[lb + e]);
    const int j0 = t >> 4;
    float v = j0 ? __fadd_rn(acc, sO1p[tid >> 4]) : acc;

    // index = cumsum - rn(k * pitch_row0[t])
    float index = __fsub_rn(v, __fmul_rn(k, pitch[t]));

    // exact trunc-remainder by 512 (bitwise == fmodf) + jnp.remainder fixup
    float q = truncf(__fmul_rn(index, 0.001953125f));
    float r = __fmaf_rn(-512.0f, q, index);
    if (r < 0.0f) r = __fadd_rn(r, 512.0f);
    if (__fsub_rn(512.0f, r) < 1e-5f) r = 0.0f;

    float lof   = floorf(r);
    float alpha = __fsub_rn(r, lof);
    int   ilo   = (int)lof;

    const int base = b * L_DIM + t;
    float acc2 = 0.0f;
    #pragma unroll
    for (int w = 0; w < N_WT; w++) {
        float2 pr = sp[w * WT_LEN + ilo];
        float wave = __fadd_rn(pr.x, __fmul_rn(alpha, __fsub_rn(pr.y, pr.x)));
        acc2 = __fadd_rn(acc2, __fmul_rn(wave, satt[tid * 11 + w]));
    }
    out[base] = __fmul_rn(acc2, env[base]);
}

// ---------------------------------------------------------------------------
// d_in order: 0 pitch, 1 envelope, 2 attention, 3 wavetables, 4 fir_h
// ---------------------------------------------------------------------------
extern "C" void kernel_launch(void* const* d_in, const int* in_sizes, int n_in,
                              void* d_out, int out_size)
{
    const float* pitch = (const float*)d_in[0];
    const float* env   = (const float*)d_in[1];
    const float* att   = (const float*)d_in[2];
    const float* wtab  = (const float*)d_in[3];
    const float* firh  = (const float*)d_in[4];
    float* out = (float*)d_out;

    cudaFuncSetAttribute(k_main, cudaFuncAttributeMaxDynamicSharedMemorySize,
                         SMEM_BYTES);

    k_s1<<<dim3(41, B_DIM), 256>>>(pitch, wtab, firh);
    k_scan<<<B_DIM, 640>>>();
    k_main<<<dim3(250, B_DIM), TPB, SMEM_BYTES>>>(pitch, env, att, out);
}

// round 6
// speedup vs baseline: 1.1820x; 1.1820x over previous
#include <cuda_runtime.h>
#include <cstdint>

// Problem constants
#define B_DIM   16
#define L_DIM   160000
#define N_WT    10
#define WT_LEN  512
#define FIR_TAPS 31
#define WT_TOT  (N_WT * WT_LEN)

// Blocked-scan parameters (XLA ReduceWindowRewriter, base_length = 16)
#define NS1 10000
#define NS2 625
#define NS3 40
#define NS4 3

#define TPB 640            // k_main threads per block (160000 / 640 = 250)

__device__ __forceinline__ float KF() { return (float)(512.0 / 16000.0); }

// Scratch
__device__ float g_S1[B_DIM][NS1];   // 16-block sums of increments
__device__ float g_S2[B_DIM][NS2];   // 16-block sums of S1
__device__ float g_O2[B_DIM][NS2];   // composed inclusive scan at level 2
__device__ float g_O1[B_DIM][NS1];   // composed inclusive scan at level 1
__device__ float g_wt[WT_TOT];       // FIR-filtered wavetables

// ---------------------------------------------------------------------------
// k_s1: S1 + S2 via coalesced smem staging (pad-17 -> conflict-free LDS).
// Strict sequential rn sums, identical rounding to the verified chain.
// Block x==40,y==0 does the FIR.  Blocks x<40 cover S1[x*250 .. x*250+249]
// (250 entries = 4000 pitch values each; 40*250 = 10000 exactly).
// ---------------------------------------------------------------------------
__global__ void k_s1(const float* __restrict__ pitch,
                     const float* __restrict__ wtab,
                     const float* __restrict__ firh)
{
    __shared__ float st[250 * 17];          // padded staging (17000 B)
    __shared__ float s2b[256];
    __shared__ float sh[FIR_TAPS];

    if (blockIdx.x == 40) {                 // FIR block
        if (blockIdx.y != 0) return;
        if (threadIdx.x < FIR_TAPS) sh[threadIdx.x] = firh[threadIdx.x];
        __syncthreads();
        for (int idx = threadIdx.x; idx < WT_TOT; idx += blockDim.x) {
            int w = idx >> 9;
            int i = idx & 511;
            const float* row = wtab + w * WT_LEN;
            float s = 0.0f;
            #pragma unroll
            for (int k = 0; k < FIR_TAPS; k++) {
                int j = (i + k - 15 + WT_LEN) & 511;
                s = __fadd_rn(s, __fmul_rn(row[j], sh[k]));
            }
            g_wt[idx] = s;
        }
        return;
    }

    const int b   = blockIdx.y;
    const int tid = threadIdx.x;
    const float k = KF();

    // coalesced load of 4000 pitch values, pre-multiplied, pad-17 scatter
    const float* P = pitch + b * L_DIM + blockIdx.x * 4000;
    for (int i = tid; i < 4000; i += 256) {
        float v = __fmul_rn(k, P[i]);
        st[(i >> 4) * 17 + (i & 15)] = v;
    }
    __syncthreads();

    // S1: strict sequential sum of 16 staged increments
    float acc = 0.0f;
    if (tid < 250) {
        const float* row = st + tid * 17;
        #pragma unroll
        for (int e = 0; e < 16; e++)
            acc = __fadd_rn(acc, row[e]);
        g_S1[b][blockIdx.x * 250 + tid] = acc;
    }
    s2b[tid] = acc;   // tid >= 250 holds 0.0f (never read for valid j2)
    __syncthreads();

    // S2: this block owns S1 entries [x*250, x*250+250); the aligned
    // 16-blocks fully inside are j2 in [ceil(x*250/16), floor((x*250+250)/16)).
    // To keep it simple and always in-bounds, recompute S2 from global S1 in
    // a separate pass is avoided; instead only blocks where x*250 is NOT
    // 16-aligned skip boundary-straddling groups — those are covered by the
    // neighbor block.  Each 16-group j2 is computed by the block containing
    // its FIRST element.
    {
        int first = blockIdx.x * 250;
        int j2lo = (first + 15) >> 4;          // first group starting in tile
        if (first == 0) j2lo = 0;
        int j2hi = (first + 250 + 15) >> 4;    // groups starting before tile end
        for (int j2 = j2lo + tid; j2 < j2hi && j2 < NS2; j2 += 256) {
            int s = j2 << 4;                   // global S1 start of this group
            if (s < first) continue;
            float a2 = 0.0f;
            #pragma unroll
            for (int e = 0; e < 16; e++) {
                int gi = s + e - first;        // index within tile
                float x = (gi < 250) ? s2b[gi] : 0.0f;
                // straddling groups: tail elements live in the next tile.
                a2 = __fadd_rn(a2, x);
            }
            // Only emit groups fully inside this tile; straddlers are
            // recomputed by k_s2fix below via global memory.
            if (s + 16 <= first + 250) g_S2[b][j2] = a2;
        }
    }
}

// ---------------------------------------------------------------------------
// k_s2fix: the ~2 straddling 16-groups per tile boundary (s < first+250 <
// s+16) — recompute from global S1.  Tiny kernel: 625 groups checked, only
// those straddling a 250-boundary are rewritten.
// ---------------------------------------------------------------------------
__global__ void k_s2fix()
{
    const int b  = blockIdx.y;
    const int j2 = blockIdx.x * 256 + threadIdx.x;
    if (j2 >= NS2) return;
    int s = j2 << 4;
    int tile_of_start = s / 250;
    int tile_of_end   = (s + 15) / 250;
    if (tile_of_start == tile_of_end) return;   // fully inside one tile: done
    float a2 = 0.0f;
    #pragma unroll
    for (int e = 0; e < 16; e++)
        a2 = __fadd_rn(a2, g_S1[b][s + e]);
    g_S2[b][j2] = a2;
}

// ---------------------------------------------------------------------------
// k_scan: per-row top-level composition: S2 -> S3 -> S4 -> O4 -> O3 -> O2.
// ---------------------------------------------------------------------------
__global__ void k_scan()
{
    __shared__ float sS2[NS2];
    __shared__ float sS3[NS3];
    __shared__ float sS4[NS4];
    __shared__ float sO4[NS4];
    __shared__ float sO3[NS3];

    const int b   = blockIdx.x;
    const int tid = threadIdx.x;

    if (tid < NS2) sS2[tid] = g_S2[b][tid];
    __syncthreads();

    if (tid < NS3) {
        float acc = 0.0f;
        for (int e = 0; e < 16; e++) {
            int idx = (tid << 4) + e;
            if (idx < NS2) acc = __fadd_rn(acc, sS2[idx]);
        }
        sS3[tid] = acc;
    }
    __syncthreads();

    if (tid < NS4) {
        float acc = 0.0f;
        for (int e = 0; e < 16; e++) {
            int idx = (tid << 4) + e;
            if (idx < NS3) acc = __fadd_rn(acc, sS3[idx]);
        }
        sS4[tid] = acc;
    }
    __syncthreads();

    if (tid == 0) {
        float acc = 0.0f;
        for (int m = 0; m < NS4; m++) {
            acc = __fadd_rn(acc, sS4[m]);
            sO4[m] = acc;
        }
    }
    __syncthreads();

    if (tid < NS3) {
        int blk = tid >> 4;
        float acc = 0.0f;
        for (int m = (blk << 4); m <= tid; m++)
            acc = __fadd_rn(acc, sS3[m]);
        sO3[tid] = blk ? __fadd_rn(acc, sO4[blk - 1]) : acc;
    }
    __syncthreads();

    if (tid < NS2) {
        int blk = tid >> 4;
        float acc = 0.0f;
        for (int m = (blk << 4); m <= tid; m++)
            acc = __fadd_rn(acc, sS2[m]);
        g_O2[b][tid] = blk ? __fadd_rn(acc, sO3[blk - 1]) : acc;
    }
}

// ---------------------------------------------------------------------------
// k_o1: materialize O1 in parallel.  Block = 256 S1 entries (16-aligned).
//   O1[m] = seqsum(S1[(m&~15) .. m])  (+ O2[m>>4 - 1] if m >= 16)
// ---------------------------------------------------------------------------
__global__ void k_o1()
{
    __shared__ float s1t[256];
    __shared__ float so2[16];

    const int b   = blockIdx.y;
    const int tid = threadIdx.x;
    const int m   = blockIdx.x * 256 + tid;

    if (m < NS1) s1t[tid] = g_S1[b][m];
    if (tid < 16) {
        int blk = blockIdx.x * 16 + tid;
        so2[tid] = (blk > 0 && blk <= NS2) ? g_O2[b][blk - 1] : 0.0f;
    }
    __syncthreads();

    if (m < NS1) {
        const int lb = tid & ~15;
        const int r0 = tid & 15;
        float acc = 0.0f;
        for (int e = 0; e <= r0; e++)
            acc = __fadd_rn(acc, s1t[lb + e]);
        g_O1[b][m] = (m >> 4) ? __fadd_rn(acc, so2[tid >> 4]) : acc;
    }
}

// ---------------------------------------------------------------------------
// k_main (R4 version, verified 51.3us / rel_err 1.379e-7)
// ---------------------------------------------------------------------------
__global__ void __launch_bounds__(TPB) k_main(
        const float* __restrict__ pitch,
        const float* __restrict__ env,
        const float* __restrict__ att,
        float* __restrict__ out)
{
    __shared__ float2 sp[WT_TOT];
    __shared__ float  sinc[TPB];

    const int tid = threadIdx.x;
    const int b   = blockIdx.y;
    const int t   = blockIdx.x * TPB + tid;
    const float k = KF();

    for (int i = tid; i < WT_TOT; i += TPB) {
        int base_w = i & ~511;
        int j = i & 511;
        sp[i] = make_float2(g_wt[i], g_wt[base_w | ((j + 1) & 511)]);
    }

    sinc[tid] = __fmul_rn(k, pitch[b * L_DIM + t]);
    __syncthreads();

    const int r0 = tid & 15;
    const int lb = tid & ~15;
    float acc = 0.0f;
    for (int e = 0; e <= r0; e++)
        acc = __fadd_rn(acc, sinc[lb + e]);
    const int j0 = t >> 4;
    float v = j0 ? __fadd_rn(acc, g_O1[b][j0 - 1]) : acc;

    float index = __fsub_rn(v, __fmul_rn(k, pitch[t]));

    float q = truncf(__fmul_rn(index, 0.001953125f));
    float r = __fmaf_rn(-512.0f, q, index);
    if (r < 0.0f) r = __fadd_rn(r, 512.0f);
    if (__fsub_rn(512.0f, r) < 1e-5f) r = 0.0f;

    float lof   = floorf(r);
    float alpha = __fsub_rn(r, lof);
    int   ilo   = (int)lof;

    const int base = b * L_DIM + t;
    const float2* ap = (const float2*)(att + (size_t)base * N_WT);
    float2 a0 = ap[0], a1 = ap[1], a2 = ap[2], a3 = ap[3], a4 = ap[4];
    float aw[N_WT] = {a0.x, a0.y, a1.x, a1.y, a2.x, a2.y, a3.x, a3.y, a4.x, a4.y};

    float acc2 = 0.0f;
    #pragma unroll
    for (int w = 0; w < N_WT; w++) {
        float2 pr = sp[w * WT_LEN + ilo];
        float wave = __fadd_rn(pr.x, __fmul_rn(alpha, __fsub_rn(pr.y, pr.x)));
        acc2 = __fadd_rn(acc2, __fmul_rn(wave, aw[w]));
    }
    out[base] = __fmul_rn(acc2, env[base]);
}

// ---------------------------------------------------------------------------
// d_in order: 0 pitch, 1 envelope, 2 attention, 3 wavetables, 4 fir_h
// ---------------------------------------------------------------------------
extern "C" void kernel_launch(void* const* d_in, const int* in_sizes, int n_in,
                              void* d_out, int out_size)
{
    const float* pitch = (const float*)d_in[0];
    const float* env   = (const float*)d_in[1];
    const float* att   = (const float*)d_in[2];
    const float* wtab  = (const float*)d_in[3];
    const float* firh  = (const float*)d_in[4];
    float* out = (float*)d_out;

    k_s1<<<dim3(41, B_DIM), 256>>>(pitch, wtab, firh);
    k_s2fix<<<dim3(3, B_DIM), 256>>>();
    k_scan<<<B_DIM, 640>>>();
    k_o1<<<dim3(40, B_DIM), 256>>>();
    k_main<<<dim3(250, B_DIM), TPB>>>(pitch, env, att, out);
}